// round 10
// baseline (speedup 1.0000x reference)
#include <cuda_runtime.h>
#include <math.h>

#define BATCH_SAMPLES 320000
#define NFRAMES 1000
#define HOP 320
#define N2 512
#define NMELS 128
#define PREEMPH 0.97f

typedef unsigned long long u64;

// ---- global tables (rebuilt every launch; deterministic) ----
__device__ float2 g_win2[400];   // hann window pairs, index p-56
__device__ float2 g_tw[257];     // exp(-i*pi*k/512)
__device__ float  g_u[512];      // per-bin up-slope weight
__device__ int    g_seg[132];    // segment starts

__global__ void setup_kernel() {
    __shared__ int s_m[512];
    int tid = threadIdx.x;  // 256
    float* gw = reinterpret_cast<float*>(g_win2);
    for (int n = tid; n < 800; n += 256)
        gw[n] = 0.5f - 0.5f * __cosf((2.0f * (float)M_PI / 799.0f) * (float)n);
    for (int k = tid; k < 257; k += 256) {
        float s, c;
        __sincosf(-((float)M_PI / 512.0f) * (float)k, &s, &c);
        g_tw[k] = make_float2(c, s);
    }
    float mel_high = 1127.0f * logf(1.0f + 16000.0f / 700.0f);
    float invd = 129.0f / mel_high;
    for (int f = tid; f < 512; f += 256) {
        float melf = 1127.0f * logf(1.0f + (float)f * (31.25f / 700.0f));
        float md = melf * invd;
        int m = (int)floorf(md);
        g_u[f] = md - (float)m;
        s_m[f] = m;
    }
    __syncthreads();
    for (int f = tid; f < 512; f += 256) {
        int m0 = s_m[f];
        int mp = (f == 0) ? -1 : s_m[f - 1];
        for (int m = mp + 1; m <= m0; ++m) g_seg[m] = f;
        if (f == 511) for (int m = m0 + 1; m <= 131; ++m) g_seg[m] = 512;
    }
}

// ---- packed f32x2 helpers ----
__device__ __forceinline__ u64 pk(float a, float b) {
    u64 r; asm("mov.b64 %0, {%1, %2};" : "=l"(r)
               : "r"(__float_as_uint(a)), "r"(__float_as_uint(b)));
    return r;
}
__device__ __forceinline__ float2 upk(u64 v) {
    unsigned lo, hi; asm("mov.b64 {%0, %1}, %2;" : "=r"(lo), "=r"(hi) : "l"(v));
    return make_float2(__uint_as_float(lo), __uint_as_float(hi));
}
__device__ __forceinline__ u64 fadd2(u64 a, u64 b) {
    u64 r; asm("add.rn.f32x2 %0, %1, %2;" : "=l"(r) : "l"(a), "l"(b)); return r;
}
__device__ __forceinline__ u64 fsub2(u64 a, u64 b) {
    u64 r; asm("sub.rn.f32x2 %0, %1, %2;" : "=l"(r) : "l"(a), "l"(b)); return r;
}
__device__ __forceinline__ u64 fmul2(u64 a, u64 b) {
    u64 r; asm("mul.rn.f32x2 %0, %1, %2;" : "=l"(r) : "l"(a), "l"(b)); return r;
}
__device__ __forceinline__ u64 ffma2(u64 a, u64 b, u64 c) {
    u64 r; asm("fma.rn.f32x2 %0, %1, %2, %3;" : "=l"(r) : "l"(a), "l"(b), "l"(c)); return r;
}

// bank-skewed addressing over 16B slots
__device__ __forceinline__ int phys(int i) { return i + (i >> 3); }

// 8-point DFT on packed pairs; no negations (add/sub folded)
__device__ __forceinline__ void dft8_2(u64* r, u64* i) {
    const u64 S22 = pk(0.70710678118654752f, 0.70710678118654752f);
    u64 br0 = fadd2(r[0], r[4]), bi0 = fadd2(i[0], i[4]);
    u64 br4 = fsub2(r[0], r[4]), bi4 = fsub2(i[0], i[4]);
    u64 t1r = fsub2(r[1], r[5]), t1i = fsub2(i[1], i[5]);
    u64 br1 = fadd2(r[1], r[5]), bi1 = fadd2(i[1], i[5]);
    u64 t2r = fsub2(r[2], r[6]), t2i = fsub2(i[2], i[6]);
    u64 br2 = fadd2(r[2], r[6]), bi2 = fadd2(i[2], i[6]);
    u64 t3r = fsub2(r[3], r[7]), t3i = fsub2(i[3], i[7]);
    u64 br3 = fadd2(r[3], r[7]), bi3 = fadd2(i[3], i[7]);
    u64 br5 = fmul2(S22, fadd2(t1r, t1i));
    u64 bi5 = fmul2(S22, fsub2(t1i, t1r));
    u64 p7r = fmul2(S22, fsub2(t3i, t3r));
    u64 p7e = fmul2(S22, fadd2(t3r, t3i));   // bi7 = -p7e
    u64 c0r = fadd2(br0, br2), c0i = fadd2(bi0, bi2);
    u64 c2r = fsub2(br0, br2), c2i = fsub2(bi0, bi2);
    u64 c1r = fadd2(br1, br3), c1i = fadd2(bi1, bi3);
    u64 d1r = fsub2(br1, br3), d1i = fsub2(bi1, bi3);
    u64 c4r = fadd2(br4, t2i), c4i = fsub2(bi4, t2r);
    u64 c6r = fsub2(br4, t2i), c6i = fadd2(bi4, t2r);
    u64 c5r = fadd2(br5, p7r), c5i = fsub2(bi5, p7e);
    u64 d3r = fsub2(br5, p7r), d3i = fadd2(bi5, p7e);
    r[0] = fadd2(c0r, c1r);  i[0] = fadd2(c0i, c1i);
    r[4] = fsub2(c0r, c1r);  i[4] = fsub2(c0i, c1i);
    r[2] = fadd2(c2r, d1i);  i[2] = fsub2(c2i, d1r);
    r[6] = fsub2(c2r, d1i);  i[6] = fadd2(c2i, d1r);
    r[1] = fadd2(c4r, c5r);  i[1] = fadd2(c4i, c5i);
    r[5] = fsub2(c4r, c5r);  i[5] = fsub2(c4i, c5i);
    r[3] = fadd2(c6r, d3i);  i[3] = fsub2(c6i, d3r);
    r[7] = fsub2(c6r, d3i);  i[7] = fadd2(c6i, d3r);
}

__device__ __forceinline__ void twiddle8_2(u64* ar, u64* ai, u64 cw, u64 sw) {
    u64 cwr = cw, cwi = sw;
    #pragma unroll
    for (int k = 1; k < 8; ++k) {
        u64 tr = fsub2(fmul2(ar[k], cwr), fmul2(ai[k], cwi));
        ai[k]  = ffma2(ar[k], cwi, fmul2(ai[k], cwr));
        ar[k]  = tr;
        u64 nr = fsub2(fmul2(cwr, cw), fmul2(cwi, sw));
        cwi    = ffma2(cwr, sw, fmul2(cwi, cw));
        cwr    = nr;
    }
}

__device__ __forceinline__ float yval(const float* __restrict__ xb, int i) {
    return (i >= 0 && i <= BATCH_SAMPLES - 2) ? (xb[i + 1] - PREEMPH * xb[i]) : 0.0f;
}

// 64 threads = one frame pair (frames 2*bx, 2*bx+1) via packed f32x2
__global__ __launch_bounds__(64, 14) void logmel_kernel(
    const float* __restrict__ x,
    float* __restrict__ out)
{
    __shared__ ulonglong2 sz[578];    // (re2, im2); split overwrites in place with (p2, u*p2)
    __shared__ float      s_u[512];

    const int lane = threadIdx.x;     // 0..63
    const int t0   = blockIdx.x * 2;  // frames t0, t0+1
    const int b    = blockIdx.y;
    const float* __restrict__ xb = x + (size_t)b * BATCH_SAMPLES;

    for (int i = lane; i < 512; i += 64) s_u[i] = g_u[i];

    // ---- load + preemph + window -> packed stage-1 registers ----
    const int basea = t0 * HOP - 512;
    u64 ar[8], ai[8];

    if (t0 >= 2 && t0 + 1 <= 998) {
        #pragma unroll
        for (int m = 0; m < 8; ++m) {
            int p = lane + (m << 6);
            if (p >= 56 && p < 456) {
                int iaa = basea + 2 * p;
                float2 va = *reinterpret_cast<const float2*>(xb + iaa);
                float xa2 = xb[iaa + 2];
                float2 vb = *reinterpret_cast<const float2*>(xb + iaa + HOP);
                float xb2 = xb[iaa + HOP + 2];
                float2 w = __ldg(&g_win2[p - 56]);
                ar[m] = pk(w.x * (va.y - PREEMPH * va.x),
                           w.x * (vb.y - PREEMPH * vb.x));
                ai[m] = pk(w.y * (xa2 - PREEMPH * va.y),
                           w.y * (xb2 - PREEMPH * vb.y));
            } else { ar[m] = 0ULL; ai[m] = 0ULL; }
        }
    } else {
        #pragma unroll
        for (int m = 0; m < 8; ++m) {
            int p = lane + (m << 6);
            float a0 = 0.0f, a1 = 0.0f, b0 = 0.0f, b1 = 0.0f;
            if (p >= 56 && p < 456) {
                float2 w = __ldg(&g_win2[p - 56]);
                a0 = w.x * yval(xb, basea + 2 * p);
                a1 = w.y * yval(xb, basea + 2 * p + 1);
                b0 = w.x * yval(xb, basea + HOP + 2 * p);
                b1 = w.y * yval(xb, basea + HOP + 2 * p + 1);
            }
            ar[m] = pk(a0, b0); ai[m] = pk(a1, b1);
        }
    }

    // ---- stage 1: span 64 ----
    dft8_2(ar, ai);
    {
        float2 w = __ldg(&g_tw[2 * lane]);
        twiddle8_2(ar, ai, pk(w.x, w.x), pk(w.y, w.y));
    }
    #pragma unroll
    for (int k = 0; k < 8; ++k)
        sz[phys(lane + (k << 6))] = make_ulonglong2(ar[k], ai[k]);
    __syncthreads();

    // ---- stage 2: span 8 ----
    {
        const int G = lane >> 3, p = lane & 7;
        const int b0 = (G << 6) + p;
        #pragma unroll
        for (int m = 0; m < 8; ++m) {
            ulonglong2 v = sz[phys(b0 + (m << 3))];
            ar[m] = v.x; ai[m] = v.y;
        }
        dft8_2(ar, ai);
        float2 w = __ldg(&g_tw[p << 4]);
        twiddle8_2(ar, ai, pk(w.x, w.x), pk(w.y, w.y));
        #pragma unroll
        for (int k = 0; k < 8; ++k)
            sz[phys(b0 + (k << 3))] = make_ulonglong2(ar[k], ai[k]);
    }
    __syncthreads();

    // ---- stage 3: span 1; store in FREQUENCY order ----
    {
        const int b0 = lane << 3;
        #pragma unroll
        for (int m = 0; m < 8; ++m) {
            ulonglong2 v = sz[phys(b0 + m)];
            ar[m] = v.x; ai[m] = v.y;
        }
        __syncthreads();   // all loads done before scatter
        dft8_2(ar, ai);
        const int rbase = ((lane & 7) << 3) | (lane >> 3);
        #pragma unroll
        for (int k = 0; k < 8; ++k)
            sz[phys((k << 6) + rbase)] = make_ulonglong2(ar[k], ai[k]);
    }
    __syncthreads();

    // ---- real-FFT split + power; IN PLACE: slot <- (p2, u*p2) ----
    // thread owns slots {phys(k), phys(512-k)}: reads then rewrites, no races
    const u64 HALF = pk(0.5f, 0.5f);
    #pragma unroll
    for (int kq = 0; kq < 4; ++kq) {
        int k  = lane + (kq << 6);            // 0..255
        int k2 = (N2 - k) & (N2 - 1);
        ulonglong2 z = sz[phys(k)];
        ulonglong2 u = sz[phys(k2)];
        u64 xer  = fmul2(HALF, fadd2(z.x, u.x));
        u64 xei  = fmul2(HALF, fsub2(z.y, u.y));
        u64 xodr = fmul2(HALF, fadd2(z.y, u.y));
        u64 xodi = fmul2(HALF, fsub2(u.x, z.x));
        float2 w = __ldg(&g_tw[k]);
        u64 WC = pk(w.x, w.x), WS = pk(w.y, w.y);
        u64 tr = fsub2(fmul2(WC, xodr), fmul2(WS, xodi));
        u64 ti = ffma2(WC, xodi, fmul2(WS, xodr));
        u64 xr = fadd2(xer, tr), xi = fadd2(xei, ti);
        u64 yr = fsub2(xer, tr), yi = fsub2(xei, ti);
        u64 px = ffma2(xr, xr, fmul2(xi, xi));
        u64 py = ffma2(yr, yr, fmul2(yi, yi));
        float uk = s_u[k], uk2 = s_u[k2];
        sz[phys(k)]      = make_ulonglong2(px, fmul2(pk(uk, uk), px));
        // bin 512-k: for k=0 this is bin 512 -> slot phys(512)=576 (unused spare)
        sz[phys(N2 - k)] = make_ulonglong2(py, fmul2(pk(uk2, uk2), py));
    }
    if (lane == 0) {
        ulonglong2 z = sz[phys(256)];
        u64 pz = ffma2(z.x, z.x, fmul2(z.y, z.y));
        sz[phys(256)] = make_ulonglong2(pz, fmul2(pk(s_u[256], s_u[256]), pz));
    }
    __syncthreads();

    // ---- mel: mel_m = sum_{seg m} u*p + sum_{seg m+1} (p - u*p); direct STG ----
    #pragma unroll
    for (int mm = 0; mm < 2; ++mm) {
        const int m  = lane + (mm << 6);
        const int f0 = __ldg(&g_seg[m]);
        const int f1 = __ldg(&g_seg[m + 1]);
        const int f2 = __ldg(&g_seg[m + 2]);
        u64 acc = 0ULL;
        for (int f = f0; f < f1; ++f) acc = fadd2(acc, sz[phys(f)].y);
        for (int f = f1; f < f2; ++f) {
            ulonglong2 v = sz[phys(f)];
            acc = fadd2(acc, fsub2(v.x, v.y));
        }
        float2 mv = upk(acc);
        float oa = (__logf(fmaxf(mv.x, 0.0f) + 1e-5f) + 4.5f) * 0.2f;
        float ob = (__logf(fmaxf(mv.y, 0.0f) + 1e-5f) + 4.5f) * 0.2f;
        *reinterpret_cast<float2*>(
            out + ((size_t)(b * NMELS + m)) * NFRAMES + t0) = make_float2(oa, ob);
    }
}

extern "C" void kernel_launch(void* const* d_in, const int* in_sizes, int n_in,
                              void* d_out, int out_size) {
    const float* x = (const float*)d_in[0];
    // d_in[1] = fourier_basis, d_in[2] = mel_basis: both reproduced analytically
    float* out = (float*)d_out;

    int batch = in_sizes[0] / BATCH_SAMPLES;   // 32

    setup_kernel<<<1, 256>>>();

    dim3 grid(NFRAMES / 2, batch);
    logmel_kernel<<<grid, 64>>>(x, out);
}

// round 11
// speedup vs baseline: 1.0807x; 1.0807x over previous
#include <cuda_runtime.h>
#include <math.h>

#define BATCH_SAMPLES 320000
#define NFRAMES 1000
#define HOP 320
#define N2 512
#define NMELS 128
#define PREEMPH 0.97f

typedef unsigned long long u64;

// ---- global tables (rebuilt every launch; deterministic) ----
__device__ float2 g_win2[400];   // hann window pairs, index p-56
__device__ float2 g_tw[257];     // exp(-i*pi*k/512)
__device__ float  g_u[512];      // per-bin up-slope weight
__device__ int    g_seg[132];    // segment starts

__global__ void setup_kernel() {
    __shared__ int s_m[512];
    int tid = threadIdx.x;  // 256
    float* gw = reinterpret_cast<float*>(g_win2);
    for (int n = tid; n < 800; n += 256)
        gw[n] = 0.5f - 0.5f * __cosf((2.0f * (float)M_PI / 799.0f) * (float)n);
    for (int k = tid; k < 257; k += 256) {
        float s, c;
        __sincosf(-((float)M_PI / 512.0f) * (float)k, &s, &c);
        g_tw[k] = make_float2(c, s);
    }
    float mel_high = 1127.0f * logf(1.0f + 16000.0f / 700.0f);
    float invd = 129.0f / mel_high;
    for (int f = tid; f < 512; f += 256) {
        float melf = 1127.0f * logf(1.0f + (float)f * (31.25f / 700.0f));
        float md = melf * invd;
        int m = (int)floorf(md);
        g_u[f] = md - (float)m;
        s_m[f] = m;
    }
    __syncthreads();
    for (int f = tid; f < 512; f += 256) {
        int m0 = s_m[f];
        int mp = (f == 0) ? -1 : s_m[f - 1];
        for (int m = mp + 1; m <= m0; ++m) g_seg[m] = f;
        if (f == 511) for (int m = m0 + 1; m <= 131; ++m) g_seg[m] = 512;
    }
}

// ---- packed f32x2 helpers ----
__device__ __forceinline__ u64 pk(float a, float b) {
    u64 r; asm("mov.b64 %0, {%1, %2};" : "=l"(r)
               : "r"(__float_as_uint(a)), "r"(__float_as_uint(b)));
    return r;
}
__device__ __forceinline__ float2 upk(u64 v) {
    unsigned lo, hi; asm("mov.b64 {%0, %1}, %2;" : "=r"(lo), "=r"(hi) : "l"(v));
    return make_float2(__uint_as_float(lo), __uint_as_float(hi));
}
__device__ __forceinline__ u64 fadd2(u64 a, u64 b) {
    u64 r; asm("add.rn.f32x2 %0, %1, %2;" : "=l"(r) : "l"(a), "l"(b)); return r;
}
__device__ __forceinline__ u64 fsub2(u64 a, u64 b) {
    u64 r; asm("sub.rn.f32x2 %0, %1, %2;" : "=l"(r) : "l"(a), "l"(b)); return r;
}
__device__ __forceinline__ u64 fmul2(u64 a, u64 b) {
    u64 r; asm("mul.rn.f32x2 %0, %1, %2;" : "=l"(r) : "l"(a), "l"(b)); return r;
}
__device__ __forceinline__ u64 ffma2(u64 a, u64 b, u64 c) {
    u64 r; asm("fma.rn.f32x2 %0, %1, %2, %3;" : "=l"(r) : "l"(a), "l"(b), "l"(c)); return r;
}

// bank-skewed addressing over 16B slots
__device__ __forceinline__ int phys(int i) { return i + (i >> 3); }

// 8-point DFT on packed pairs; no negations (add/sub folded)
__device__ __forceinline__ void dft8_2(u64* r, u64* i) {
    const u64 S22 = pk(0.70710678118654752f, 0.70710678118654752f);
    u64 br0 = fadd2(r[0], r[4]), bi0 = fadd2(i[0], i[4]);
    u64 br4 = fsub2(r[0], r[4]), bi4 = fsub2(i[0], i[4]);
    u64 t1r = fsub2(r[1], r[5]), t1i = fsub2(i[1], i[5]);
    u64 br1 = fadd2(r[1], r[5]), bi1 = fadd2(i[1], i[5]);
    u64 t2r = fsub2(r[2], r[6]), t2i = fsub2(i[2], i[6]);
    u64 br2 = fadd2(r[2], r[6]), bi2 = fadd2(i[2], i[6]);
    u64 t3r = fsub2(r[3], r[7]), t3i = fsub2(i[3], i[7]);
    u64 br3 = fadd2(r[3], r[7]), bi3 = fadd2(i[3], i[7]);
    u64 br5 = fmul2(S22, fadd2(t1r, t1i));
    u64 bi5 = fmul2(S22, fsub2(t1i, t1r));
    u64 p7r = fmul2(S22, fsub2(t3i, t3r));
    u64 p7e = fmul2(S22, fadd2(t3r, t3i));   // bi7 = -p7e
    u64 c0r = fadd2(br0, br2), c0i = fadd2(bi0, bi2);
    u64 c2r = fsub2(br0, br2), c2i = fsub2(bi0, bi2);
    u64 c1r = fadd2(br1, br3), c1i = fadd2(bi1, bi3);
    u64 d1r = fsub2(br1, br3), d1i = fsub2(bi1, bi3);
    u64 c4r = fadd2(br4, t2i), c4i = fsub2(bi4, t2r);
    u64 c6r = fsub2(br4, t2i), c6i = fadd2(bi4, t2r);
    u64 c5r = fadd2(br5, p7r), c5i = fsub2(bi5, p7e);
    u64 d3r = fsub2(br5, p7r), d3i = fadd2(bi5, p7e);
    r[0] = fadd2(c0r, c1r);  i[0] = fadd2(c0i, c1i);
    r[4] = fsub2(c0r, c1r);  i[4] = fsub2(c0i, c1i);
    r[2] = fadd2(c2r, d1i);  i[2] = fsub2(c2i, d1r);
    r[6] = fsub2(c2r, d1i);  i[6] = fadd2(c2i, d1r);
    r[1] = fadd2(c4r, c5r);  i[1] = fadd2(c4i, c5i);
    r[5] = fsub2(c4r, c5r);  i[5] = fsub2(c4i, c5i);
    r[3] = fadd2(c6r, d3i);  i[3] = fsub2(c6i, d3r);
    r[7] = fsub2(c6r, d3i);  i[7] = fadd2(c6i, d3r);
}

__device__ __forceinline__ void twiddle8_2(u64* ar, u64* ai, u64 cw, u64 sw) {
    u64 cwr = cw, cwi = sw;
    #pragma unroll
    for (int k = 1; k < 8; ++k) {
        u64 tr = fsub2(fmul2(ar[k], cwr), fmul2(ai[k], cwi));
        ai[k]  = ffma2(ar[k], cwi, fmul2(ai[k], cwr));
        ar[k]  = tr;
        u64 nr = fsub2(fmul2(cwr, cw), fmul2(cwi, sw));
        cwi    = ffma2(cwr, sw, fmul2(cwi, cw));
        cwr    = nr;
    }
}

__device__ __forceinline__ float yval(const float* __restrict__ xb, int i) {
    return (i >= 0 && i <= BATCH_SAMPLES - 2) ? (xb[i + 1] - PREEMPH * xb[i]) : 0.0f;
}

// 64 threads = one frame pair (frames 2*bx, 2*bx+1) via packed f32x2
__global__ __launch_bounds__(64, 14) void logmel_kernel(
    const float* __restrict__ x,
    float* __restrict__ out)
{
    __shared__ ulonglong2 sz[578];    // (re2, im2) FFT workspace
    __shared__ u64        spw[513];   // packed power per bin
    __shared__ float      s_u[512];

    const int lane = threadIdx.x;     // 0..63
    const int t0   = blockIdx.x * 2;  // frames t0, t0+1
    const int b    = blockIdx.y;
    const float* __restrict__ xb = x + (size_t)b * BATCH_SAMPLES;

    for (int i = lane; i < 512; i += 64) s_u[i] = g_u[i];

    // ---- load + preemph + window -> packed stage-1 registers ----
    const int basea = t0 * HOP - 512;
    u64 ar[8], ai[8];

    if (t0 >= 2 && t0 + 1 <= 998) {
        #pragma unroll
        for (int m = 0; m < 8; ++m) {
            int p = lane + (m << 6);
            if (p >= 56 && p < 456) {
                int iaa = basea + 2 * p;
                float2 va = *reinterpret_cast<const float2*>(xb + iaa);
                float xa2 = xb[iaa + 2];
                float2 vb = *reinterpret_cast<const float2*>(xb + iaa + HOP);
                float xb2 = xb[iaa + HOP + 2];
                float2 w = __ldg(&g_win2[p - 56]);
                ar[m] = pk(w.x * (va.y - PREEMPH * va.x),
                           w.x * (vb.y - PREEMPH * vb.x));
                ai[m] = pk(w.y * (xa2 - PREEMPH * va.y),
                           w.y * (xb2 - PREEMPH * vb.y));
            } else { ar[m] = 0ULL; ai[m] = 0ULL; }
        }
    } else {
        #pragma unroll
        for (int m = 0; m < 8; ++m) {
            int p = lane + (m << 6);
            float a0 = 0.0f, a1 = 0.0f, b0 = 0.0f, b1 = 0.0f;
            if (p >= 56 && p < 456) {
                float2 w = __ldg(&g_win2[p - 56]);
                a0 = w.x * yval(xb, basea + 2 * p);
                a1 = w.y * yval(xb, basea + 2 * p + 1);
                b0 = w.x * yval(xb, basea + HOP + 2 * p);
                b1 = w.y * yval(xb, basea + HOP + 2 * p + 1);
            }
            ar[m] = pk(a0, b0); ai[m] = pk(a1, b1);
        }
    }

    // ---- stage 1: span 64 ----
    dft8_2(ar, ai);
    {
        float2 w = __ldg(&g_tw[2 * lane]);
        twiddle8_2(ar, ai, pk(w.x, w.x), pk(w.y, w.y));
    }
    #pragma unroll
    for (int k = 0; k < 8; ++k)
        sz[phys(lane + (k << 6))] = make_ulonglong2(ar[k], ai[k]);
    __syncthreads();

    // ---- stage 2: span 8 ----
    {
        const int G = lane >> 3, p = lane & 7;
        const int b0 = (G << 6) + p;
        #pragma unroll
        for (int m = 0; m < 8; ++m) {
            ulonglong2 v = sz[phys(b0 + (m << 3))];
            ar[m] = v.x; ai[m] = v.y;
        }
        dft8_2(ar, ai);
        float2 w = __ldg(&g_tw[p << 4]);
        twiddle8_2(ar, ai, pk(w.x, w.x), pk(w.y, w.y));
        #pragma unroll
        for (int k = 0; k < 8; ++k)
            sz[phys(b0 + (k << 3))] = make_ulonglong2(ar[k], ai[k]);
    }
    __syncthreads();

    // ---- stage 3: span 1; store in FREQUENCY order ----
    {
        const int b0 = lane << 3;
        #pragma unroll
        for (int m = 0; m < 8; ++m) {
            ulonglong2 v = sz[phys(b0 + m)];
            ar[m] = v.x; ai[m] = v.y;
        }
        __syncthreads();   // all loads done before scatter
        dft8_2(ar, ai);
        const int rbase = ((lane & 7) << 3) | (lane >> 3);
        #pragma unroll
        for (int k = 0; k < 8; ++k)
            sz[phys((k << 6) + rbase)] = make_ulonglong2(ar[k], ai[k]);
    }
    __syncthreads();

    // ---- real-FFT split + power -> spw (packed power only) ----
    const u64 HALF = pk(0.5f, 0.5f);
    #pragma unroll
    for (int kq = 0; kq < 4; ++kq) {
        int k  = lane + (kq << 6);            // 0..255
        int k2 = (N2 - k) & (N2 - 1);
        ulonglong2 z = sz[phys(k)];
        ulonglong2 u = sz[phys(k2)];
        u64 xer  = fmul2(HALF, fadd2(z.x, u.x));
        u64 xei  = fmul2(HALF, fsub2(z.y, u.y));
        u64 xodr = fmul2(HALF, fadd2(z.y, u.y));
        u64 xodi = fmul2(HALF, fsub2(u.x, z.x));
        float2 w = __ldg(&g_tw[k]);
        u64 WC = pk(w.x, w.x), WS = pk(w.y, w.y);
        u64 tr = fsub2(fmul2(WC, xodr), fmul2(WS, xodi));
        u64 ti = ffma2(WC, xodi, fmul2(WS, xodr));
        u64 xr = fadd2(xer, tr), xi = fadd2(xei, ti);
        u64 yr = fsub2(xer, tr), yi = fsub2(xei, ti);
        spw[k]      = ffma2(xr, xr, fmul2(xi, xi));
        spw[N2 - k] = ffma2(yr, yr, fmul2(yi, yi));
    }
    if (lane == 0) {
        ulonglong2 z = sz[phys(256)];
        spw[256] = ffma2(z.x, z.x, fmul2(z.y, z.y));
    }
    __syncthreads();

    // ---- mel: thread owns mels (2*lane, 2*lane+1); each bin read once ----
    // per segment s: P = sum p, U = sum u*p; mel_m = U_m + (P_{m+1} - U_{m+1})
    {
        const int m0 = 2 * lane;
        const int fa = __ldg(&g_seg[m0]);
        const int fb = __ldg(&g_seg[m0 + 1]);
        const int fc = __ldg(&g_seg[m0 + 2]);
        u64 P0 = 0ULL, U0 = 0ULL, P1 = 0ULL, U1 = 0ULL;
        for (int f = fa; f < fb; ++f) {
            u64 p = spw[f]; float uf = s_u[f];
            P0 = fadd2(P0, p); U0 = ffma2(pk(uf, uf), p, U0);
        }
        for (int f = fb; f < fc; ++f) {
            u64 p = spw[f]; float uf = s_u[f];
            P1 = fadd2(P1, p); U1 = ffma2(pk(uf, uf), p, U1);
        }
        u64 D0 = fsub2(P0, U0);                       // this thread's first-segment down part
        u64 D2 = __shfl_down_sync(0xffffffffu, D0, 1);
        if ((lane & 31) == 31) {                      // warp boundary: recompute directly
            const int fd = __ldg(&g_seg[m0 + 3]);
            u64 P2 = 0ULL, U2 = 0ULL;
            for (int f = fc; f < fd; ++f) {
                u64 p = spw[f]; float uf = s_u[f];
                P2 = fadd2(P2, p); U2 = ffma2(pk(uf, uf), p, U2);
            }
            D2 = fsub2(P2, U2);
        }
        u64 mel0 = fadd2(U0, fsub2(P1, U1));
        u64 mel1 = fadd2(U1, D2);
        float2 v0 = upk(mel0), v1 = upk(mel1);
        float o00 = (__logf(fmaxf(v0.x, 0.0f) + 1e-5f) + 4.5f) * 0.2f;
        float o01 = (__logf(fmaxf(v0.y, 0.0f) + 1e-5f) + 4.5f) * 0.2f;
        float o10 = (__logf(fmaxf(v1.x, 0.0f) + 1e-5f) + 4.5f) * 0.2f;
        float o11 = (__logf(fmaxf(v1.y, 0.0f) + 1e-5f) + 4.5f) * 0.2f;
        float* o = out + ((size_t)(b * NMELS + m0)) * NFRAMES + t0;
        *reinterpret_cast<float2*>(o)           = make_float2(o00, o01);
        *reinterpret_cast<float2*>(o + NFRAMES) = make_float2(o10, o11);
    }
}

extern "C" void kernel_launch(void* const* d_in, const int* in_sizes, int n_in,
                              void* d_out, int out_size) {
    const float* x = (const float*)d_in[0];
    // d_in[1] = fourier_basis, d_in[2] = mel_basis: both reproduced analytically
    float* out = (float*)d_out;

    int batch = in_sizes[0] / BATCH_SAMPLES;   // 32

    setup_kernel<<<1, 256>>>();

    dim3 grid(NFRAMES / 2, batch);
    logmel_kernel<<<grid, 64>>>(x, out);
}